// round 1
// baseline (speedup 1.0000x reference)
#include <cuda_runtime.h>

// Problem constants (from reference): E=500000, P=4000000, D=U=64.
// Scratch for transformed features (feat @ W): 500000*64 floats = 128 MB.
// __device__ global (allocation inside kernel_launch is forbidden).
__device__ float g_xform[500000 * 64];

// ---------------------------------------------------------------------------
// Kernel 1: g_xform = feat @ W ; also initialize out[e,:] = bias (so the
// scatter kernel can accumulate directly into d_out).
// One block computes a 64-row x 64-col output tile. 256 threads, each owns a
// 4x4 register tile. A-tile stored transposed in smem (pad 65 to kill bank
// conflicts); W-tile row-major so the per-k column read is a clean LDS.128.
// ---------------------------------------------------------------------------
__global__ void __launch_bounds__(256) transform_kernel(
    const float* __restrict__ feat,   // [E, 64]
    const float* __restrict__ W,      // [64, 64]
    const float* __restrict__ bias,   // [64]
    float* __restrict__ out,          // [E, 64]  (init with bias here)
    int E)
{
    __shared__ float sW[64 * 64];     // sW[k*64 + u]
    __shared__ float sA[64 * 65];     // sA[k*65 + r]  (transposed, padded)

    const int tid  = threadIdx.x;
    const int row0 = blockIdx.x * 64;

    // Load W (coalesced, direct copy: already [k][u] row-major).
    #pragma unroll
    for (int i = tid; i < 64 * 64; i += 256)
        sW[i] = W[i];

    // Load A tile, transposing into smem. Consecutive tid -> consecutive k of
    // one row -> coalesced 256B global reads.
    #pragma unroll
    for (int i = tid; i < 64 * 64; i += 256) {
        int r = i >> 6;
        int k = i & 63;
        int row = row0 + r;
        sA[k * 65 + r] = (row < E) ? feat[row * 64 + k] : 0.0f;
    }
    __syncthreads();

    const int rt = tid >> 4;   // 0..15 : which 4-row strip
    const int ct = tid & 15;   // 0..15 : which 4-col strip

    float acc[4][4];
    #pragma unroll
    for (int i = 0; i < 4; i++)
        #pragma unroll
        for (int j = 0; j < 4; j++)
            acc[i][j] = 0.0f;

    #pragma unroll
    for (int k = 0; k < 64; k++) {
        const float a0 = sA[k * 65 + rt * 4 + 0];
        const float a1 = sA[k * 65 + rt * 4 + 1];
        const float a2 = sA[k * 65 + rt * 4 + 2];
        const float a3 = sA[k * 65 + rt * 4 + 3];
        const float4 w = *reinterpret_cast<const float4*>(&sW[k * 64 + ct * 4]);

        acc[0][0] += a0 * w.x; acc[0][1] += a0 * w.y; acc[0][2] += a0 * w.z; acc[0][3] += a0 * w.w;
        acc[1][0] += a1 * w.x; acc[1][1] += a1 * w.y; acc[1][2] += a1 * w.z; acc[1][3] += a1 * w.w;
        acc[2][0] += a2 * w.x; acc[2][1] += a2 * w.y; acc[2][2] += a2 * w.z; acc[2][3] += a2 * w.w;
        acc[3][0] += a3 * w.x; acc[3][1] += a3 * w.y; acc[3][2] += a3 * w.z; acc[3][3] += a3 * w.w;
    }

    const float4 b = *reinterpret_cast<const float4*>(&bias[ct * 4]);

    #pragma unroll
    for (int i = 0; i < 4; i++) {
        int row = row0 + rt * 4 + i;
        if (row < E) {
            float4 v;
            v.x = acc[i][0]; v.y = acc[i][1]; v.z = acc[i][2]; v.w = acc[i][3];
            *reinterpret_cast<float4*>(&g_xform[row * 64 + ct * 4]) = v;
            *reinterpret_cast<float4*>(&out[row * 64 + ct * 4])     = b;  // bias init
        }
    }
}

// ---------------------------------------------------------------------------
// Kernel 2: for each pair p: out[dst, :] += g_xform[src, :]
// 16 threads per pair, one float4 each. red.global.add.v4.f32 (no return
// value -> REDG path, no round trip). Within a warp the 16 threads of a pair
// touch 256 contiguous bytes of both the gather source and the scatter
// destination.
// ---------------------------------------------------------------------------
__global__ void __launch_bounds__(256) scatter_kernel(
    const int2* __restrict__ nbr,    // [P] : {dst, src}
    float* __restrict__ out,         // [E, 64]
    int P)
{
    const int i = blockIdx.x * 256 + threadIdx.x;
    const int p = i >> 4;
    if (p >= P) return;
    const int c = (i & 15) * 4;

    const int2 e = nbr[p];           // e.x = receiving edge (dst), e.y = neighbor (src)

    const float4 v = *reinterpret_cast<const float4*>(&g_xform[e.y * 64 + c]);
    float* dst = &out[e.x * 64 + c];

    asm volatile("red.global.add.v4.f32 [%0], {%1, %2, %3, %4};"
                 :: "l"(dst), "f"(v.x), "f"(v.y), "f"(v.z), "f"(v.w)
                 : "memory");
}

// ---------------------------------------------------------------------------
extern "C" void kernel_launch(void* const* d_in, const int* in_sizes, int n_in,
                              void* d_out, int out_size)
{
    const float* feat = (const float*)d_in[0];   // [E, 64] f32
    const int*   nbr  = (const int*)d_in[1];     // [P, 2]  i32
    const float* W    = (const float*)d_in[2];   // [64, 64] f32
    const float* bias = (const float*)d_in[3];   // [64] f32
    float* out = (float*)d_out;                  // [E, 64] f32

    const int E = in_sizes[0] / 64;
    const int P = in_sizes[1] / 2;

    // Step 1: transform + bias-init of out.
    const int blocksA = (E + 63) / 64;
    transform_kernel<<<blocksA, 256>>>(feat, W, bias, out, E);

    // Step 2: scatter-accumulate transformed neighbor rows into out.
    const long long total = (long long)P * 16;
    const int blocksC = (int)((total + 255) / 256);
    scatter_kernel<<<blocksC, 256>>>((const int2*)nbr, out, P);
}